// round 12
// baseline (speedup 1.0000x reference)
#include <cuda_runtime.h>

#define NN 4096
#define MM 4096
#define DD 8

typedef unsigned long long u64;

// out[i][j] = exp2( an[i] + bn[j] + sum_d a[i][d]*b[j][d] )
//   a = x/scale * sqrt(log2 e),  an = -0.5||a||^2 + log2(var),  bn = -0.5||b||^2

__device__ __forceinline__ u64 fma2(u64 a, u64 b, u64 c) {
    u64 d; asm("fma.rn.f32x2 %0, %1, %2, %3;" : "=l"(d) : "l"(a), "l"(b), "l"(c)); return d;
}
__device__ __forceinline__ u64 add2(u64 a, u64 b) {
    u64 d; asm("add.rn.f32x2 %0, %1, %2;" : "=l"(d) : "l"(a), "l"(b)); return d;
}
__device__ __forceinline__ u64 pack2(float x, float y) {
    u64 r; asm("mov.b64 %0, {%1,%2};" : "=l"(r) : "f"(x), "f"(y)); return r;
}
__device__ __forceinline__ float lo2(u64 v) { return __uint_as_float((unsigned)v); }
__device__ __forceinline__ float hi2(u64 v) { return __uint_as_float((unsigned)(v >> 32)); }
__device__ __forceinline__ float ex2(float x) {
    float r; asm("ex2.approx.f32 %0, %1;" : "=f"(r) : "f"(x)); return r;
}

// Fused kernel. CTA tile: 64 (i) x 256 (j), 256 threads, TWO j-halves of the
// proven optimal per-thread micro-tile (4i x 8j, 12B smem-read/output).
// Half-0's epilogue (MUFU+STG burst) overlaps half-1's mainloop issue.
//   i = bi + 4*ti + u (u=0..3), ti = tid>>4; tj = tid&15
//   half h: j quads at bj + 128h + 4*tj and bj + 128h + 64 + 4*tj
__global__ __launch_bounds__(256, 4) void rbf_main(
    const float* __restrict__ x,
    const float* __restrict__ xx,
    const float* __restrict__ log_scale,
    const float* __restrict__ log_variance,
    float* __restrict__ out)
{
    __shared__ float  sAf[DD][64];      // d-major a            (2KB)
    __shared__ float  sB [DD][256];     // d-major b, 2 halves  (8KB)
    __shared__ float  sAn[64];
    __shared__ float  sBn[256];

    const int bi = blockIdx.y * 64;
    const int bj = blockIdx.x * 256;
    const int tid = threadIdx.x;

    // per-thread scale factors (broadcast LDG, no barrier needed)
    float sinv[DD];
    {
        const float4 l0 = ((const float4*)log_scale)[0];
        const float4 l1 = ((const float4*)log_scale)[1];
        const float k = -1.4426950408889634f;
        sinv[0] = ex2(l0.x * k) * 1.2011224087864498f;
        sinv[1] = ex2(l0.y * k) * 1.2011224087864498f;
        sinv[2] = ex2(l0.z * k) * 1.2011224087864498f;
        sinv[3] = ex2(l0.w * k) * 1.2011224087864498f;
        sinv[4] = ex2(l1.x * k) * 1.2011224087864498f;
        sinv[5] = ex2(l1.y * k) * 1.2011224087864498f;
        sinv[6] = ex2(l1.z * k) * 1.2011224087864498f;
        sinv[7] = ex2(l1.w * k) * 1.2011224087864498f;
    }

    // ---- prep: every thread does one B col; threads < 64 also one A row ----
    {
        const int j = tid;                       // 0..255
        const float4 p0 = ((const float4*)(xx + (size_t)(bj + j) * DD))[0];
        const float4 p1 = ((const float4*)(xx + (size_t)(bj + j) * DD))[1];
        float b[DD];
        b[0] = p0.x * sinv[0]; b[1] = p0.y * sinv[1];
        b[2] = p0.z * sinv[2]; b[3] = p0.w * sinv[3];
        b[4] = p1.x * sinv[4]; b[5] = p1.y * sinv[5];
        b[6] = p1.z * sinv[6]; b[7] = p1.w * sinv[7];
        float s = 0.f;
        #pragma unroll
        for (int d = 0; d < DD; d++) { sB[d][j] = b[d]; s = fmaf(b[d], b[d], s); }
        sBn[j] = -0.5f * s;
    }
    if (tid < 64) {
        const float4 p0 = ((const float4*)(x + (size_t)(bi + tid) * DD))[0];
        const float4 p1 = ((const float4*)(x + (size_t)(bi + tid) * DD))[1];
        float a[DD];
        a[0] = p0.x * sinv[0]; a[1] = p0.y * sinv[1];
        a[2] = p0.z * sinv[2]; a[3] = p0.w * sinv[3];
        a[4] = p1.x * sinv[4]; a[5] = p1.y * sinv[5];
        a[6] = p1.z * sinv[6]; a[7] = p1.w * sinv[7];
        float s = 0.f;
        #pragma unroll
        for (int d = 0; d < DD; d++) { sAf[d][tid] = a[d]; s = fmaf(a[d], a[d], s); }
        sAn[tid] = fmaf(-0.5f, s, log_variance[0] * 1.4426950408889634f);
    }
    __syncthreads();

    const int ti = tid >> 4;   // 0..15, i = 4*ti + u
    const int tj = tid & 15;   // 0..15

    #pragma unroll
    for (int h = 0; h < 2; h++) {
        const int jb = 128 * h;

        u64 e[4][4];
        {
            const ulonglong2 bnA = *(const ulonglong2*)&sBn[jb + 4 * tj];
            const ulonglong2 bnB = *(const ulonglong2*)&sBn[jb + 64 + 4 * tj];
            const float4 anq = *(const float4*)&sAn[4 * ti];
            const u64 anv[4] = {pack2(anq.x, anq.x), pack2(anq.y, anq.y),
                                pack2(anq.z, anq.z), pack2(anq.w, anq.w)};
            #pragma unroll
            for (int u = 0; u < 4; u++) {
                e[u][0] = add2(anv[u], bnA.x);
                e[u][1] = add2(anv[u], bnA.y);
                e[u][2] = add2(anv[u], bnB.x);
                e[u][3] = add2(anv[u], bnB.y);
            }
        }

        #pragma unroll
        for (int d = 0; d < DD; d++) {
            const ulonglong2 bA = *(const ulonglong2*)&sB[d][jb + 4 * tj];
            const ulonglong2 bB = *(const ulonglong2*)&sB[d][jb + 64 + 4 * tj];
            const float4 aq = *(const float4*)&sAf[d][4 * ti];
            const u64 av[4] = {pack2(aq.x, aq.x), pack2(aq.y, aq.y),
                               pack2(aq.z, aq.z), pack2(aq.w, aq.w)};
            #pragma unroll
            for (int u = 0; u < 4; u++) {
                e[u][0] = fma2(av[u], bA.x, e[u][0]);
                e[u][1] = fma2(av[u], bA.y, e[u][1]);
                e[u][2] = fma2(av[u], bB.x, e[u][2]);
                e[u][3] = fma2(av[u], bB.y, e[u][3]);
            }
        }

        float* p0 = out + (size_t)(bi + 4 * ti) * MM + bj + jb + 4 * tj;
        #pragma unroll
        for (int u = 0; u < 4; u++) {
            float4 rA, rB;
            rA.x = ex2(lo2(e[u][0])); rA.y = ex2(hi2(e[u][0]));
            rA.z = ex2(lo2(e[u][1])); rA.w = ex2(hi2(e[u][1]));
            rB.x = ex2(lo2(e[u][2])); rB.y = ex2(hi2(e[u][2]));
            rB.z = ex2(lo2(e[u][3])); rB.w = ex2(hi2(e[u][3]));
            *(float4*)(p0)      = rA;
            *(float4*)(p0 + 64) = rB;
            p0 += MM;
        }
    }
}

extern "C" void kernel_launch(void* const* d_in, const int* in_sizes, int n_in,
                              void* d_out, int out_size) {
    const float* x      = (const float*)d_in[0];
    const float* xx     = (const float*)d_in[1];
    const float* lscale = (const float*)d_in[2];
    const float* lvar   = (const float*)d_in[3];
    float* out          = (float*)d_out;

    dim3 grid(MM / 256, NN / 64);
    rbf_main<<<grid, 256>>>(x, xx, lscale, lvar, out);
}

// round 13
// speedup vs baseline: 2.4206x; 2.4206x over previous
#include <cuda_runtime.h>

#define NN 4096
#define MM 4096
#define DD 8

typedef unsigned long long u64;

// out[i][j] = exp2( an[i] + bn[j] + sum_d a[i][d]*b[j][d] )
//   a = x/scale * sqrt(log2 e),  an = -0.5||a||^2 + log2(var),  bn = -0.5||b||^2

__device__ __forceinline__ u64 fma2(u64 a, u64 b, u64 c) {
    u64 d; asm("fma.rn.f32x2 %0, %1, %2, %3;" : "=l"(d) : "l"(a), "l"(b), "l"(c)); return d;
}
__device__ __forceinline__ u64 add2(u64 a, u64 b) {
    u64 d; asm("add.rn.f32x2 %0, %1, %2;" : "=l"(d) : "l"(a), "l"(b)); return d;
}
__device__ __forceinline__ u64 pack2(float x, float y) {
    u64 r; asm("mov.b64 %0, {%1,%2};" : "=l"(r) : "f"(x), "f"(y)); return r;
}
__device__ __forceinline__ float lo2(u64 v) { return __uint_as_float((unsigned)v); }
__device__ __forceinline__ float hi2(u64 v) { return __uint_as_float((unsigned)(v >> 32)); }
__device__ __forceinline__ float ex2(float x) {
    float r; asm("ex2.approx.f32 %0, %1;" : "=f"(r) : "f"(x)); return r;
}

// Fused kernel (R7 structure). CTA tile: 64 (i) x 128 (j), 256 threads,
// 32 outputs/thread (4i x 8j, 12B smem-read per output).
//   i = bi + 4*ti + u (u=0..3);  j quads at bj + 4*tj and bj + 64 + 4*tj.
// Single barrier: scale factors live in registers (broadcast LDG).
__global__ __launch_bounds__(256, 4) void rbf_main(
    const float* __restrict__ x,
    const float* __restrict__ xx,
    const float* __restrict__ log_scale,
    const float* __restrict__ log_variance,
    float* __restrict__ out)
{
    __shared__ float  sAf[DD][64];      // d-major a, packed floats  (2KB)
    __shared__ float  sB [DD][128];     // d-major b                 (4KB)
    __shared__ float  sAn[64];
    __shared__ float  sBn[128];

    const int bi = blockIdx.y * 64;
    const int bj = blockIdx.x * 128;
    const int tid = threadIdx.x;

    // per-thread scale factors (broadcast LDG, no barrier needed)
    float sinv[DD];
    {
        const float4 l0 = ((const float4*)log_scale)[0];
        const float4 l1 = ((const float4*)log_scale)[1];
        const float k = -1.4426950408889634f;
        const float c = 1.2011224087864498f;     // sqrt(log2 e)
        sinv[0] = ex2(l0.x * k) * c; sinv[1] = ex2(l0.y * k) * c;
        sinv[2] = ex2(l0.z * k) * c; sinv[3] = ex2(l0.w * k) * c;
        sinv[4] = ex2(l1.x * k) * c; sinv[5] = ex2(l1.y * k) * c;
        sinv[6] = ex2(l1.z * k) * c; sinv[7] = ex2(l1.w * k) * c;
    }

    // ---- prep: tid<128 -> B col tid ; tid in [128,192) -> A row tid-128 ----
    if (tid < 128) {
        const int j = tid;
        const float4 p0 = ((const float4*)(xx + (size_t)(bj + j) * DD))[0];
        const float4 p1 = ((const float4*)(xx + (size_t)(bj + j) * DD))[1];
        float b[DD];
        b[0] = p0.x * sinv[0]; b[1] = p0.y * sinv[1];
        b[2] = p0.z * sinv[2]; b[3] = p0.w * sinv[3];
        b[4] = p1.x * sinv[4]; b[5] = p1.y * sinv[5];
        b[6] = p1.z * sinv[6]; b[7] = p1.w * sinv[7];
        float s = 0.f;
        #pragma unroll
        for (int d = 0; d < DD; d++) { sB[d][j] = b[d]; s = fmaf(b[d], b[d], s); }
        sBn[j] = -0.5f * s;
    } else if (tid < 192) {
        const int r = tid - 128;
        const float4 p0 = ((const float4*)(x + (size_t)(bi + r) * DD))[0];
        const float4 p1 = ((const float4*)(x + (size_t)(bi + r) * DD))[1];
        float a[DD];
        a[0] = p0.x * sinv[0]; a[1] = p0.y * sinv[1];
        a[2] = p0.z * sinv[2]; a[3] = p0.w * sinv[3];
        a[4] = p1.x * sinv[4]; a[5] = p1.y * sinv[5];
        a[6] = p1.z * sinv[6]; a[7] = p1.w * sinv[7];
        float s = 0.f;
        #pragma unroll
        for (int d = 0; d < DD; d++) { sAf[d][r] = a[d]; s = fmaf(a[d], a[d], s); }
        sAn[r] = fmaf(-0.5f, s, log_variance[0] * 1.4426950408889634f);
    }
    __syncthreads();

    // ---- main compute ----
    const int ti = tid >> 4;   // 0..15, i = 4*ti + u
    const int tj = tid & 15;   // 0..15

    u64 e[4][4];
    {
        const ulonglong2 bnA = *(const ulonglong2*)&sBn[4 * tj];
        const ulonglong2 bnB = *(const ulonglong2*)&sBn[64 + 4 * tj];
        const float4 anq = *(const float4*)&sAn[4 * ti];            // 1 LDS.128
        const u64 anv[4] = {pack2(anq.x, anq.x), pack2(anq.y, anq.y),
                            pack2(anq.z, anq.z), pack2(anq.w, anq.w)};
        #pragma unroll
        for (int u = 0; u < 4; u++) {
            e[u][0] = add2(anv[u], bnA.x);
            e[u][1] = add2(anv[u], bnA.y);
            e[u][2] = add2(anv[u], bnB.x);
            e[u][3] = add2(anv[u], bnB.y);
        }
    }

    #pragma unroll
    for (int d = 0; d < DD; d++) {
        const ulonglong2 bA = *(const ulonglong2*)&sB[d][4 * tj];       // 1 LDS.128
        const ulonglong2 bB = *(const ulonglong2*)&sB[d][64 + 4 * tj];  // 1 LDS.128
        const float4 aq = *(const float4*)&sAf[d][4 * ti];              // 1 LDS.128
        const u64 av[4] = {pack2(aq.x, aq.x), pack2(aq.y, aq.y),
                           pack2(aq.z, aq.z), pack2(aq.w, aq.w)};
        #pragma unroll
        for (int u = 0; u < 4; u++) {
            e[u][0] = fma2(av[u], bA.x, e[u][0]);
            e[u][1] = fma2(av[u], bA.y, e[u][1]);
            e[u][2] = fma2(av[u], bB.x, e[u][2]);
            e[u][3] = fma2(av[u], bB.y, e[u][3]);
        }
    }

    // epilogue: exp2 + vector stores; rows bi + 4*ti + u consecutive
    float* p0 = out + (size_t)(bi + 4 * ti) * MM + bj + 4 * tj;
    #pragma unroll
    for (int u = 0; u < 4; u++) {
        float4 rA, rB;
        rA.x = ex2(lo2(e[u][0])); rA.y = ex2(hi2(e[u][0]));
        rA.z = ex2(lo2(e[u][1])); rA.w = ex2(hi2(e[u][1]));
        rB.x = ex2(lo2(e[u][2])); rB.y = ex2(hi2(e[u][2]));
        rB.z = ex2(lo2(e[u][3])); rB.w = ex2(hi2(e[u][3]));
        *(float4*)(p0)      = rA;
        *(float4*)(p0 + 64) = rB;
        p0 += MM;
    }
}

extern "C" void kernel_launch(void* const* d_in, const int* in_sizes, int n_in,
                              void* d_out, int out_size) {
    const float* x      = (const float*)d_in[0];
    const float* xx     = (const float*)d_in[1];
    const float* lscale = (const float*)d_in[2];
    const float* lvar   = (const float*)d_in[3];
    float* out          = (float*)d_out;

    dim3 grid(MM / 128, NN / 64);
    rbf_main<<<grid, 256>>>(x, xx, lscale, lvar, out);
}